// round 13
// baseline (speedup 1.0000x reference)
#include <cuda_runtime.h>
#include <cuda_bf16.h>

// ---- static problem config ----
#define NIMG 32
#define HH   1024
#define WW   1024
#define BHW  16                 // pool window
#define BSTR 14                 // block stride
#define BC   73                 // blocks per spatial dim
#define BC2  (BC*BC)            // 5329
#define NROW (NIMG*BC)          // 2336  (n, bh) row-blocks
#define NBLK (NROW*BC)          // 170528 total blocks
#define OUT_ELEMS (NBLK*3)      // 511584 floats = 127896 float4 (exact)
#define OUT_VEC4  (OUT_ELEMS/4)
#define THRESH 0.9f
#define W4     (WW/4)

// scratch (device globals — no allocation allowed)
__device__ unsigned g_bitmap[NROW * 3];   // 96-bit active mask per (n,bh) row
__device__ unsigned g_count[NROW];        // popcount per row

__device__ __forceinline__ float4 fmax4(float4 a, float4 b)
{
    return make_float4(fmaxf(a.x, b.x), fmaxf(a.y, b.y),
                       fmaxf(a.z, b.z), fmaxf(a.w, b.w));
}

// ---------------------------------------------------------------------------
// K1: one CTA per (n, bh) with 128 threads (2 float4 columns per thread) so
// the grid is a SINGLE wave (2336x128 = 299k threads, 16 CTAs/SM) — R12's
// 256-thread version needed 2 waves and paid the load-latency critical path
// twice. MONOTONE EARLY EXIT (proven R12): a block is active iff any pixel
// in its window exceeds THRESH, so the bitmap is monotone in rows read.
// Chunk 1 = 4 rows (8 front-batched loads/thread, MLP=8) then checkpoint:
// ~92% of CTAs find all 73 windows active and stop. Survivors read ALL
// remaining rows in one chunk and re-run the checkpoint (final answer either
// way). Zero is the exact identity (zero padding, mask values in [0,1)).
// ---------------------------------------------------------------------------
__global__ __launch_bounds__(128) void pool_kernel(const float* __restrict__ mask)
{
    const int cta = blockIdx.x;          // n*BC + bh
    const int n   = cta / BC;
    const int bh  = cta % BC;
    const int tid = threadIdx.x;

    __shared__ float4   sv4[256];        // 1024 column maxima
    __shared__ unsigned sbm[3];

    // padded window [bh*14, bh*14+16) -> unpadded rows [bh*14-1, bh*14+15)
    const int h0 = bh * BSTR - 1;
    const int hs = (h0 < 0) ? 0 : h0;
    const int he = (h0 + BHW < HH) ? (h0 + BHW) : HH;
    const int total_rows = he - hs;      // 15 (bh==0) or 16, always >= 15

    const float4* base = (const float4*)(mask + (size_t)n * HH * WW) + hs * W4;

    // ---- chunk 1: static 4 rows, 8 independent loads ----
    float4 a0, a1;
    {
        float4 x0 = base[0 * W4 + tid];
        float4 y0 = base[0 * W4 + 128 + tid];
        float4 x1 = base[1 * W4 + tid];
        float4 y1 = base[1 * W4 + 128 + tid];
        float4 x2 = base[2 * W4 + tid];
        float4 y2 = base[2 * W4 + 128 + tid];
        float4 x3 = base[3 * W4 + tid];
        float4 y3 = base[3 * W4 + 128 + tid];
        a0 = fmax4(fmax4(x0, x1), fmax4(x2, x3));
        a1 = fmax4(fmax4(y0, y1), fmax4(y2, y3));
    }

    // ---- checkpoint 1 ----
    sv4[tid]       = a0;
    sv4[tid + 128] = a1;
    __syncthreads();
    {
        const float* sv = (const float*)sv4;
        if (tid < 96) {                   // warps 0,1,2
            float m = 0.f;
            if (tid < BC) {
                const int w0 = tid * BSTR - 1;
                const int ws = (w0 < 0) ? 0 : w0;
                const int we = (w0 + BHW < WW) ? (w0 + BHW) : WW;
                for (int w = ws; w < we; ++w) m = fmaxf(m, sv[w]);
            }
            unsigned b = __ballot_sync(0xFFFFFFFFu, m > THRESH);
            if ((tid & 31) == 0) sbm[tid >> 5] = b;
        }
    }
    __syncthreads();

    const bool done1 = (sbm[0] == 0xFFFFFFFFu) &
                       (sbm[1] == 0xFFFFFFFFu) &
                       (sbm[2] == 0x1FFu);

    if (!done1) {
        // ---- chunk 2: all remaining rows (11 or 12), one pass ----
        #pragma unroll 4
        for (int h = 4; h < total_rows; ++h) {
            a0 = fmax4(a0, base[h * W4 + tid]);
            a1 = fmax4(a1, base[h * W4 + 128 + tid]);
        }

        sv4[tid]       = a0;
        sv4[tid + 128] = a1;
        __syncthreads();
        const float* sv = (const float*)sv4;
        if (tid < 96) {
            float m = 0.f;
            if (tid < BC) {
                const int w0 = tid * BSTR - 1;
                const int ws = (w0 < 0) ? 0 : w0;
                const int we = (w0 + BHW < WW) ? (w0 + BHW) : WW;
                for (int w = ws; w < we; ++w) m = fmaxf(m, sv[w]);
            }
            unsigned b = __ballot_sync(0xFFFFFFFFu, m > THRESH);
            if ((tid & 31) == 0) sbm[tid >> 5] = b;
        }
        __syncthreads();
    }

    if (tid < 3) g_bitmap[cta * 3 + tid] = sbm[tid];
    if (tid == 0)
        g_count[cta] = (unsigned)(__popc(sbm[0]) + __popc(sbm[1]) + __popc(sbm[2]));
}

// ---------------------------------------------------------------------------
// K2: write (exact R10/R12 structure — 2.7us wall). Phase A: SUM of the 2336
// counts -> total. Dense path (total == NBLK): pure divmod, no offsets.
// Sparse fallback: full smem scan + bitmap bit-ranking (never taken here).
// Phase B: 2 float4 slots per thread, register-triple phase branch.
// ---------------------------------------------------------------------------
#define WT      256
#define WSLOTS  2
#define WGRID   ((OUT_VEC4 + WT*WSLOTS - 1) / (WT*WSLOTS))   // 250
#define WCHUNK  ((NROW + WT - 1) / WT)    // 10

__device__ __forceinline__ int nth_set_bit(unsigned w, int n)  // n-th (0-based)
{
    return (int)__fns(w, 0, n + 1);
}

__device__ __forceinline__ void resolve_dense(unsigned p,
                                              float& x, float& y, float& z)
{
    unsigned n = p / BC2;
    unsigned r = p - n * BC2;
    x = (float)n;
    y = (float)(r / BC);
    z = (float)(r % BC);
}

__device__ __forceinline__ void resolve_gen(unsigned p, unsigned total,
                                            const unsigned* __restrict__ s_off,
                                            float& x, float& y, float& z)
{
    if (p >= total) { x = -1.f; y = -1.f; z = -1.f; return; }

    int lo = 0, hi = NROW - 1;
    while (lo < hi) {
        int mid = (lo + hi + 1) >> 1;
        if (s_off[mid] <= p) lo = mid; else hi = mid - 1;
    }
    const int row  = lo;
    int       rank = (int)(p - s_off[row]);

    unsigned w0 = g_bitmap[row * 3 + 0];
    unsigned w1 = g_bitmap[row * 3 + 1];
    unsigned w2 = g_bitmap[row * 3 + 2];
    int c0 = __popc(w0), c1 = __popc(w1);
    int bw;
    if (rank < c0)            bw = nth_set_bit(w0, rank);
    else if (rank - c0 < c1)  bw = 32 + nth_set_bit(w1, rank - c0);
    else                      bw = 64 + nth_set_bit(w2, rank - c0 - c1);

    x = (float)(row / BC);
    y = (float)(row % BC);
    z = (float)bw;
}

__device__ __forceinline__ float4 phase_pack(int phase,
                                             float a0, float a1, float a2,
                                             float b0, float b1, float b2)
{
    if (phase == 0) return make_float4(a0, a1, a2, b0);
    if (phase == 1) return make_float4(a1, a2, b0, b1);
    return make_float4(a2, b0, b1, b2);
}

__global__ __launch_bounds__(WT) void write_kernel(float4* __restrict__ out)
{
    __shared__ unsigned s_off[NROW];          // sparse fallback only
    __shared__ unsigned s_wsum[WT / 32];
    __shared__ unsigned s_total;

    const int tid = threadIdx.x;

    // ---- Phase A: total = sum(g_count) ----
    unsigned v = 0;
    #pragma unroll
    for (int k = 0; k < WCHUNK; ++k) {
        int i = k * WT + tid;
        if (i < NROW) v += g_count[i];
    }
    #pragma unroll
    for (int o = 16; o >= 1; o >>= 1)
        v += __shfl_down_sync(0xFFFFFFFFu, v, o);
    if ((tid & 31) == 0) s_wsum[tid >> 5] = v;
    __syncthreads();
    if (tid == 0) {
        unsigned t = 0;
        #pragma unroll
        for (int w = 0; w < WT / 32; ++w) t += s_wsum[w];
        s_total = t;
    }
    __syncthreads();
    const unsigned total = s_total;

    const bool dense = (total == NBLK);
    if (!dense) {
        // ---- sparse fallback: full exclusive scan into s_off ----
        for (int i = tid; i < NROW; i += WT) s_off[i] = g_count[i];
        __syncthreads();
        __shared__ unsigned s_part[WT];
        const int start = tid * WCHUNK;
        const int end   = (start + WCHUNK < NROW) ? (start + WCHUNK) : NROW;
        unsigned sum = 0;
        for (int i = start; i < end; ++i) sum += s_off[i];
        s_part[tid] = sum;
        __syncthreads();
        for (int off = 1; off < WT; off <<= 1) {
            unsigned t = (tid >= off) ? s_part[tid - off] : 0u;
            __syncthreads();
            s_part[tid] += t;
            __syncthreads();
        }
        unsigned run = (tid > 0) ? s_part[tid - 1] : 0u;
        for (int i = start; i < end; ++i) {
            unsigned c = s_off[i];
            s_off[i] = run;
            run += c;
        }
        __syncthreads();
    }

    // ---- Phase B: WSLOTS float4 slots per thread ----
    #pragma unroll
    for (int k = 0; k < WSLOTS; ++k) {
        const int slot = (blockIdx.x * WSLOTS + k) * WT + tid;
        if (slot >= OUT_VEC4) continue;

        const unsigned p0 = ((unsigned)slot * 4u) / 3u;
        float a0, a1, a2, b0, b1, b2;
        if (dense) {
            resolve_dense(p0, a0, a1, a2);
            if (p0 + 1u < NBLK) resolve_dense(p0 + 1u, b0, b1, b2);
            else { b0 = -1.f; b1 = -1.f; b2 = -1.f; }
        } else {
            resolve_gen(p0,      total, s_off, a0, a1, a2);
            resolve_gen(p0 + 1u, total, s_off, b0, b1, b2);
        }

        out[slot] = phase_pack(slot % 3, a0, a1, a2, b0, b1, b2);
    }
}

// ---------------------------------------------------------------------------
extern "C" void kernel_launch(void* const* d_in, const int* in_sizes, int n_in,
                              void* d_out, int out_size)
{
    const float* mask = (const float*)d_in[0];

    pool_kernel<<<NROW, 128>>>(mask);
    write_kernel<<<WGRID, WT>>>((float4*)d_out);
}